// round 15
// baseline (speedup 1.0000x reference)
#include <cuda_runtime.h>
#include <cstdint>

// MultiDense y[b,n,o] = sum_i x[b,n,i]*A[n,o,i] + Bp[n,o]
// R15: pure fp16 GEMM, 64x64 warp tile (4 warps, block=128) for 1.5x higher
// FLOP-per-LDSM-byte; 2 CTAs/SM. X via LDG->regs->fp16 STS; A pre-converted.

#define BSZ   2048
#define NSPL  256
#define DIN   256
#define DOUT  256
#define BM    64
#define KC    64
#define NSTG  4

// smem layout (bytes), per CTA = 80 KB
#define XH0   0        // Xh fp16: 2 x 8192
#define AH0   16384    // Ah fp16: 2 x 32768
#define SMEM_TOTAL 81920

__device__ uint32_t Ah_g[(size_t)NSPL * DOUT * DIN / 2];   // 32 MB fp16 A scratch

__device__ __forceinline__ uint32_t s2u(const void* p){
    uint32_t a;
    asm("{ .reg .u64 t; cvta.to.shared.u64 t, %1; cvt.u32.u64 %0, t; }" : "=r"(a) : "l"(p));
    return a;
}
__device__ __forceinline__ void cpasync16(uint32_t s, const void* g){
    asm volatile("cp.async.cg.shared.global [%0], [%1], 16;" :: "r"(s), "l"(g));
}
__device__ __forceinline__ void sts64(uint32_t a, uint32_t v0, uint32_t v1){
    asm volatile("st.shared.v2.b32 [%0], {%1,%2};" :: "r"(a), "r"(v0), "r"(v1) : "memory");
}
__device__ __forceinline__ uint32_t cvtf16_2(float2 v){
    uint32_t h;
    asm("cvt.rn.f16x2.f32 %0, %1, %2;" : "=r"(h) : "f"(v.y), "f"(v.x));
    return h;
}
__device__ __forceinline__ void ldsm4(uint32_t a, uint32_t& r0, uint32_t& r1,
                                      uint32_t& r2, uint32_t& r3){
    asm volatile("ldmatrix.sync.aligned.m8n8.x4.shared.b16 {%0,%1,%2,%3}, [%4];"
        : "=r"(r0), "=r"(r1), "=r"(r2), "=r"(r3) : "r"(a));
}
__device__ __forceinline__ void mma_f16(float* c, const uint32_t* a, const uint32_t* b){
    asm volatile("mma.sync.aligned.m16n8k16.row.col.f32.f16.f16.f32 "
        "{%0,%1,%2,%3}, {%4,%5,%6,%7}, {%8,%9}, {%0,%1,%2,%3};"
        : "+f"(c[0]), "+f"(c[1]), "+f"(c[2]), "+f"(c[3])
        : "r"(a[0]), "r"(a[1]), "r"(a[2]), "r"(a[3]), "r"(b[0]), "r"(b[1]));
}

// fp16 tile (128B rows): 16B chunk c (0-7) XOR (row&7); q = 4-elem quad (0-15)
#define TQOFF(row, q)  ((uint32_t)((row)*128 + (((((q)>>1) ^ ((row)&7)))<<4) + ((q)&1)*8))

// ---- pre-pass: A fp32 -> fp16 scratch ----
__global__ __launch_bounds__(256, 8)
void convertA_kernel(const float* __restrict__ A){
    size_t i = (size_t)blockIdx.x * 256 + threadIdx.x;
    const float4* s = (const float4*)A + 2*i;
    float4 v0 = s[0], v1 = s[1];
    uint4 o;
    o.x = cvtf16_2(make_float2(v0.x, v0.y));
    o.y = cvtf16_2(make_float2(v0.z, v0.w));
    o.z = cvtf16_2(make_float2(v1.x, v1.y));
    o.w = cvtf16_2(make_float2(v1.z, v1.w));
    ((uint4*)Ah_g)[i] = o;
}

__global__ __launch_bounds__(128, 2)
void multidense_mma(const float* __restrict__ x,
                    const float* __restrict__ Bp, float* __restrict__ out)
{
    extern __shared__ char smem[];
    const uint32_t sb = s2u(smem);
    const int tid  = threadIdx.x;
    const int wid  = tid >> 5, lane = tid & 31;
    const int qr   = lane >> 2, qc = lane & 3;
    const int t8   = lane >> 3, r8 = lane & 7;
    const int n    = blockIdx.y;
    const int mBase= blockIdx.x * BM;
    const int n0w  = wid * 64;             // warp n offset; m covers full 0-63

    // X loader: thread handles rows {xrow, xrow+32}, quads {xq+4j}, j=0..3
    const int xrow = tid >> 2;             // 0..31
    const int xq   = tid & 3;
    const float* xg0 = x + (size_t)(mBase + xrow) * (NSPL*DIN) + (size_t)n * DIN;
    const float* xg1 = xg0 + (size_t)32 * (NSPL*DIN);
    const char*  ag  = (const char*)Ah_g + (size_t)n * (DOUT*DIN) * 2;

    uint32_t xsts[8];
    #pragma unroll
    for (int j = 0; j < 4; ++j){
        xsts[j]   = TQOFF(xrow,      xq + 4*j);
        xsts[4+j] = TQOFF(xrow + 32, xq + 4*j);
    }

    float acc[4][8][4];
    #pragma unroll
    for (int mb = 0; mb < 4; ++mb)
        #pragma unroll
        for (int nb = 0; nb < 8; ++nb)
            #pragma unroll
            for (int e = 0; e < 4; ++e) acc[mb][nb][e] = 0.f;

    // ldmatrix per-lane bases
    uint32_t xrb[4], xsw[4], arb[4], asw[4];
    const int kax = t8 >> 1, kaa = t8 & 1;
    #pragma unroll
    for (int mb = 0; mb < 4; ++mb){
        int row = mb*16 + (t8 & 1)*8 + r8;
        xrb[mb] = sb + XH0 + (uint32_t)row*128; xsw[mb] = row & 7;
    }
    #pragma unroll
    for (int p = 0; p < 4; ++p){
        int row = n0w + p*16 + (t8 >> 1)*8 + r8;
        arb[p] = sb + AH0 + (uint32_t)row*128; asw[p] = row & 7;
    }

    auto loadA = [&](int s){
        const int b = s & 1;
        const int ks0 = s * KC;
        const uint32_t ahb = sb + AH0 + (uint32_t)b*32768;
        #pragma unroll
        for (int j = 0; j < 16; ++j){                // Ah fp16: 256 rows x 64 k
            int g = tid + 128*j, row = g >> 3, c = g & 7;
            cpasync16(ahb + (uint32_t)row*128 + (uint32_t)((c ^ (row & 7)) << 4),
                      ag + ((size_t)row*DIN + ks0 + c*8)*2);
        }
        asm volatile("cp.async.commit_group;" ::: "memory");
    };
    auto loadX = [&](int s, float4* xr){
        const int ks0 = s * KC;
        #pragma unroll
        for (int j = 0; j < 4; ++j){
            xr[j]   = *(const float4*)(xg0 + ks0 + (xq + 4*j)*4);
            xr[4+j] = *(const float4*)(xg1 + ks0 + (xq + 4*j)*4);
        }
    };
    auto cvtX = [&](const float4* xr, uint32_t* xc){
        #pragma unroll
        for (int j = 0; j < 8; ++j){
            xc[2*j]   = cvtf16_2(make_float2(xr[j].x, xr[j].y));
            xc[2*j+1] = cvtf16_2(make_float2(xr[j].z, xr[j].w));
        }
    };

    // prologue: stage 0
    float4   xr[8];
    uint32_t xc[16];
    loadX(0, xr);
    loadA(0);
    cvtX(xr, xc);

    for (int s = 0; s < NSTG; ++s){
        const int b = s & 1;
        __syncthreads();                  // XH[b] free

        {   // STS converted X(s) into XH[b]
            const uint32_t xhb = sb + XH0 + (uint32_t)b*8192;
            #pragma unroll
            for (int j = 0; j < 8; ++j)
                sts64(xhb + xsts[j], xc[2*j], xc[2*j+1]);
        }

        if (s + 1 < NSTG){ loadX(s + 1, xr); loadA(s + 1); }

        if (s + 1 < NSTG) asm volatile("cp.async.wait_group 1;" ::: "memory");
        else             asm volatile("cp.async.wait_group 0;" ::: "memory");
        __syncthreads();                  // XH[b] + AH[b] visible

        // ---- mainloop: 4 x k16 slices; 8 ldsm4 -> 32 MMA per warp-slice ----
        const uint32_t xo = (uint32_t)b*8192, ao = (uint32_t)b*32768;
        #pragma unroll
        for (int kk = 0; kk < 4; ++kk){
            const int ck = kk*2;
            uint32_t ah[8][2];
            #pragma unroll
            for (int p = 0; p < 4; ++p){
                uint32_t addr = arb[p] + ao + (uint32_t)(((ck + kaa) ^ asw[p]) << 4);
                ldsm4(addr, ah[2*p][0], ah[2*p][1], ah[2*p+1][0], ah[2*p+1][1]);
            }
            #pragma unroll
            for (int mb = 0; mb < 4; ++mb){
                uint32_t xh[4];
                uint32_t addr = xrb[mb] + xo + (uint32_t)(((ck + kax) ^ xsw[mb]) << 4);
                ldsm4(addr, xh[0], xh[1], xh[2], xh[3]);
                #pragma unroll
                for (int nb = 0; nb < 8; ++nb)
                    mma_f16(acc[mb][nb], xh, ah[nb]);
            }
        }

        if (s + 1 < NSTG) cvtX(xr, xc);   // LDG landed during mainloop
    }

    // ---- epilogue: bias + STG.64 ----
    #pragma unroll
    for (int nb = 0; nb < 8; ++nb){
        const int col = n0w + nb*8 + qc*2;
        const float2 bb = *(const float2*)(Bp + (size_t)n*DOUT + col);
        #pragma unroll
        for (int mb = 0; mb < 4; ++mb){
            const int rg0 = mBase + mb*16 + qr;
            float2 v0 = make_float2(acc[mb][nb][0] + bb.x, acc[mb][nb][1] + bb.y);
            float2 v1 = make_float2(acc[mb][nb][2] + bb.x, acc[mb][nb][3] + bb.y);
            *(float2*)(out + (size_t)rg0     *(NSPL*DOUT) + (size_t)n*DOUT + col) = v0;
            *(float2*)(out + (size_t)(rg0+8) *(NSPL*DOUT) + (size_t)n*DOUT + col) = v1;
        }
    }
}

extern "C" void kernel_launch(void* const* d_in, const int* in_sizes, int n_in,
                              void* d_out, int out_size)
{
    const float* x  = (const float*)d_in[0];
    const float* A  = (const float*)d_in[1];
    const float* Bp = (const float*)d_in[2];
    float* out = (float*)d_out;

    convertA_kernel<<<8192, 256>>>(A);

    cudaFuncSetAttribute(multidense_mma, cudaFuncAttributeMaxDynamicSharedMemorySize, SMEM_TOTAL);
    dim3 grid(BSZ / BM, NSPL);   // (32, 256) = 8192 CTAs
    multidense_mma<<<grid, 128, SMEM_TOTAL>>>(x, Bp, out);
}